// round 1
// baseline (speedup 1.0000x reference)
#include <cuda_runtime.h>

// Problem constants
#define BB 4
#define SS 2048
#define DD 1024
#define HH 16
#define HDIM 64

// Scratch (allocation-free rule: __device__ globals)
__device__ float g_Q[(size_t)BB * SS * DD];
__device__ float g_K[(size_t)BB * SS * DD];
__device__ float g_V[(size_t)BB * SS * DD];
__device__ float g_A[(size_t)BB * SS * DD];

// ---------------------------------------------------------------------------
// GEMM: C[M,N] = A[M,K] @ W[N,K]^T + bias[N]   (both A and W are K-major)
// Tile 128x128x16, 256 threads, 8x8 micro-tile.
// ---------------------------------------------------------------------------
__global__ __launch_bounds__(256) void gemm_bias_kernel(
    const float* __restrict__ A, const float* __restrict__ W,
    const float* __restrict__ bias, float* __restrict__ C,
    int M, int N, int K)
{
    __shared__ float As[16 * 132];  // [k][m], stride 132 (16B-aligned rows)
    __shared__ float Ws[16 * 132];  // [k][n]

    const int tid = threadIdx.x;
    const int tx = tid & 15, ty = tid >> 4;
    const int bm = blockIdx.y * 128;
    const int bn = blockIdx.x * 128;

    float acc[8][8];
#pragma unroll
    for (int i = 0; i < 8; i++)
#pragma unroll
        for (int j = 0; j < 8; j++) acc[i][j] = 0.f;

    for (int k0 = 0; k0 < K; k0 += 16) {
#pragma unroll
        for (int t = tid; t < 512; t += 256) {
            int m = t >> 2;
            int k4 = (t & 3) << 2;
            float4 va = *(const float4*)(A + (size_t)(bm + m) * K + k0 + k4);
            As[(k4 + 0) * 132 + m] = va.x;
            As[(k4 + 1) * 132 + m] = va.y;
            As[(k4 + 2) * 132 + m] = va.z;
            As[(k4 + 3) * 132 + m] = va.w;
            float4 vw = *(const float4*)(W + (size_t)(bn + m) * K + k0 + k4);
            Ws[(k4 + 0) * 132 + m] = vw.x;
            Ws[(k4 + 1) * 132 + m] = vw.y;
            Ws[(k4 + 2) * 132 + m] = vw.z;
            Ws[(k4 + 3) * 132 + m] = vw.w;
        }
        __syncthreads();

#pragma unroll
        for (int kk = 0; kk < 16; kk++) {
            float4 a0 = *(const float4*)&As[kk * 132 + ty * 8];
            float4 a1 = *(const float4*)&As[kk * 132 + ty * 8 + 4];
            float4 w0 = *(const float4*)&Ws[kk * 132 + tx * 8];
            float4 w1 = *(const float4*)&Ws[kk * 132 + tx * 8 + 4];
            float a[8] = {a0.x, a0.y, a0.z, a0.w, a1.x, a1.y, a1.z, a1.w};
            float w[8] = {w0.x, w0.y, w0.z, w0.w, w1.x, w1.y, w1.z, w1.w};
#pragma unroll
            for (int i = 0; i < 8; i++)
#pragma unroll
                for (int j = 0; j < 8; j++)
                    acc[i][j] = fmaf(a[i], w[j], acc[i][j]);
        }
        __syncthreads();
    }

#pragma unroll
    for (int i = 0; i < 8; i++) {
        size_t row = (size_t)(bm + ty * 8 + i) * N + bn;
#pragma unroll
        for (int j = 0; j < 8; j++)
            C[row + tx * 8 + j] = acc[i][j] + bias[bn + tx * 8 + j];
    }
}

// ---------------------------------------------------------------------------
// RoPE in-place on Q and K, [B,S,D] layout. Phase computed in fp64 so
// precision survives --use_fast_math (args up to 2047 rad).
// ---------------------------------------------------------------------------
__global__ __launch_bounds__(256) void rope_kernel(
    float* __restrict__ Qb, float* __restrict__ Kb)
{
    int idx = blockIdx.x * 256 + threadIdx.x;  // over B*S*H*32
    int i = idx & 31;
    int h = (idx >> 5) & (HH - 1);
    int bs = idx >> 9;           // b*S + s
    int s = bs & (SS - 1);

    // inv_freq = 10000^(-i/32) = exp(-i * ln(10000)/32)
    double inv_freq = exp((double)i * -0.28782313662425575);
    double phase = (double)s * inv_freq;
    double sd, cd;
    sincos(phase, &sd, &cd);
    float sn = (float)sd, cs = (float)cd;

    size_t off = (size_t)bs * DD + h * HDIM + i;

    float q1 = Qb[off], q2 = Qb[off + 32];
    Qb[off]      = q1 * cs - q2 * sn;
    Qb[off + 32] = q2 * cs + q1 * sn;

    float k1 = Kb[off], k2 = Kb[off + 32];
    Kb[off]      = k1 * cs - k2 * sn;
    Kb[off + 32] = k2 * cs + k1 * sn;
}

// ---------------------------------------------------------------------------
// Causal flash attention. BR=64 q-rows per block, BC=32 k-cols per iter.
// 256 threads: 16(ty) x 16(tx). S-tile: 4 rows x 2 cols / thread.
// O-tile:  4 rows x 4 cols / thread. Online softmax in registers.
// ---------------------------------------------------------------------------
__global__ __launch_bounds__(256) void attn_kernel(
    const float* __restrict__ Q, const float* __restrict__ K,
    const float* __restrict__ V, float* __restrict__ O)
{
    const int qt = blockIdx.x;   // q tile (0..31)
    const int h  = blockIdx.y;
    const int b  = blockIdx.z;
    const int tid = threadIdx.x;
    const int tx = tid & 15, ty = tid >> 4;

    __shared__ float Qs[64 * 68];   // transposed: Qs[d*68 + i]
    __shared__ float KP[64 * 34];   // union: Ks[d*34 + j]  /  Ps[j*68 + i] (32*68=2176=64*34)
    __shared__ float Vs[32 * 64];   // natural: Vs[j*64 + dd]

    const size_t base = ((size_t)b * SS) * DD + (size_t)h * HDIM;

    // Load Q tile, fold in softmax scale (1/sqrt(64) = 0.125)
    for (int t = tid; t < 64 * 64; t += 256) {
        int i = t >> 6, d = t & 63;
        Qs[d * 68 + i] = Q[base + (size_t)(qt * 64 + i) * DD + d] * 0.125f;
    }

    float m_r[4], l_r[4], o_r[4][4];
#pragma unroll
    for (int r = 0; r < 4; r++) {
        m_r[r] = -1e30f;
        l_r[r] = 0.f;
#pragma unroll
        for (int c = 0; c < 4; c++) o_r[r][c] = 0.f;
    }

    const int ntiles = 2 * qt + 2;
    for (int jt = 0; jt < ntiles; ++jt) {
        __syncthreads();  // previous PV done reading KP/Vs (and first-iter Q load)

        // Load K tile transposed
        for (int t = tid; t < 32 * 64; t += 256) {
            int j = t >> 6, d = t & 63;
            KP[d * 34 + j] = K[base + (size_t)(jt * 32 + j) * DD + d];
        }
        // Load V tile natural (vectorized)
        for (int t = tid; t < 32 * 16; t += 256) {
            int j = t >> 4, d4 = (t & 15) << 2;
            *(float4*)&Vs[j * 64 + d4] =
                *(const float4*)&V[base + (size_t)(jt * 32 + j) * DD + d4];
        }
        __syncthreads();

        // S = Q K^T  (per-thread 4x2)
        float s00 = 0.f, s01 = 0.f, s10 = 0.f, s11 = 0.f;
        float s20 = 0.f, s21 = 0.f, s30 = 0.f, s31 = 0.f;
#pragma unroll 8
        for (int d = 0; d < 64; ++d) {
            float4 qv = *(const float4*)&Qs[d * 68 + ty * 4];
            float2 kv = *(const float2*)&KP[d * 34 + tx * 2];
            s00 = fmaf(qv.x, kv.x, s00); s01 = fmaf(qv.x, kv.y, s01);
            s10 = fmaf(qv.y, kv.x, s10); s11 = fmaf(qv.y, kv.y, s11);
            s20 = fmaf(qv.z, kv.x, s20); s21 = fmaf(qv.z, kv.y, s21);
            s30 = fmaf(qv.w, kv.x, s30); s31 = fmaf(qv.w, kv.y, s31);
        }
        float s_reg[4][2] = {{s00, s01}, {s10, s11}, {s20, s21}, {s30, s31}};

        // Causal mask (only the last two tiles can be partially masked)
        if (jt >= 2 * qt) {
            int kbase = jt * 32 + tx * 2;
            int qbase = qt * 64 + ty * 4;
#pragma unroll
            for (int r = 0; r < 4; r++)
#pragma unroll
                for (int c = 0; c < 2; c++)
                    if (kbase + c > qbase + r) s_reg[r][c] = -1e30f;
        }

        // Row max over the 16 tx lanes (width-16 butterfly)
        float tmax[4];
#pragma unroll
        for (int r = 0; r < 4; r++) tmax[r] = fmaxf(s_reg[r][0], s_reg[r][1]);
#pragma unroll
        for (int o = 8; o > 0; o >>= 1)
#pragma unroll
            for (int r = 0; r < 4; r++)
                tmax[r] = fmaxf(tmax[r], __shfl_xor_sync(0xffffffffu, tmax[r], o, 16));

        float alpha[4], p[4][2], rs[4];
#pragma unroll
        for (int r = 0; r < 4; r++) {
            float nm = fmaxf(m_r[r], tmax[r]);
            alpha[r] = __expf(m_r[r] - nm);
            m_r[r] = nm;
            p[r][0] = __expf(s_reg[r][0] - nm);
            p[r][1] = __expf(s_reg[r][1] - nm);
            rs[r] = p[r][0] + p[r][1];
        }
#pragma unroll
        for (int o = 8; o > 0; o >>= 1)
#pragma unroll
            for (int r = 0; r < 4; r++)
                rs[r] += __shfl_xor_sync(0xffffffffu, rs[r], o, 16);
#pragma unroll
        for (int r = 0; r < 4; r++) {
            l_r[r] = l_r[r] * alpha[r] + rs[r];
#pragma unroll
            for (int c = 0; c < 4; c++) o_r[r][c] *= alpha[r];
        }

        __syncthreads();  // all threads done reading Ks before Ps overwrites
#pragma unroll
        for (int r = 0; r < 4; r++)
#pragma unroll
            for (int c = 0; c < 2; c++)
                KP[(tx * 2 + c) * 68 + ty * 4 + r] = p[r][c];
        __syncthreads();

        // O += P @ V  (per-thread 4x4)
#pragma unroll 8
        for (int j = 0; j < 32; ++j) {
            float4 pv = *(const float4*)&KP[j * 68 + ty * 4];
            float4 vv = *(const float4*)&Vs[j * 64 + tx * 4];
            o_r[0][0] = fmaf(pv.x, vv.x, o_r[0][0]);
            o_r[0][1] = fmaf(pv.x, vv.y, o_r[0][1]);
            o_r[0][2] = fmaf(pv.x, vv.z, o_r[0][2]);
            o_r[0][3] = fmaf(pv.x, vv.w, o_r[0][3]);
            o_r[1][0] = fmaf(pv.y, vv.x, o_r[1][0]);
            o_r[1][1] = fmaf(pv.y, vv.y, o_r[1][1]);
            o_r[1][2] = fmaf(pv.y, vv.z, o_r[1][2]);
            o_r[1][3] = fmaf(pv.y, vv.w, o_r[1][3]);
            o_r[2][0] = fmaf(pv.z, vv.x, o_r[2][0]);
            o_r[2][1] = fmaf(pv.z, vv.y, o_r[2][1]);
            o_r[2][2] = fmaf(pv.z, vv.z, o_r[2][2]);
            o_r[2][3] = fmaf(pv.z, vv.w, o_r[2][3]);
            o_r[3][0] = fmaf(pv.w, vv.x, o_r[3][0]);
            o_r[3][1] = fmaf(pv.w, vv.y, o_r[3][1]);
            o_r[3][2] = fmaf(pv.w, vv.z, o_r[3][2]);
            o_r[3][3] = fmaf(pv.w, vv.w, o_r[3][3]);
        }
    }

    // Epilogue: divide by l, write merged [B,S,D] layout
#pragma unroll
    for (int r = 0; r < 4; r++) {
        float inv = 1.0f / l_r[r];
        size_t row = base + (size_t)(qt * 64 + ty * 4 + r) * DD + tx * 4;
        float4 v;
        v.x = o_r[r][0] * inv;
        v.y = o_r[r][1] * inv;
        v.z = o_r[r][2] * inv;
        v.w = o_r[r][3] * inv;
        *(float4*)&O[row] = v;
    }
}

// ---------------------------------------------------------------------------
extern "C" void kernel_launch(void* const* d_in, const int* in_sizes, int n_in,
                              void* d_out, int out_size)
{
    (void)in_sizes; (void)n_in; (void)out_size;
    const float* x  = (const float*)d_in[0];
    const float* Wq = (const float*)d_in[1];
    const float* bq = (const float*)d_in[2];
    const float* Wk = (const float*)d_in[3];
    const float* bk = (const float*)d_in[4];
    const float* Wv = (const float*)d_in[5];
    const float* bv = (const float*)d_in[6];
    const float* Wo = (const float*)d_in[7];
    const float* bo = (const float*)d_in[8];
    float* out = (float*)d_out;

    float *Qp, *Kp, *Vp, *Ap;
    cudaGetSymbolAddress((void**)&Qp, g_Q);
    cudaGetSymbolAddress((void**)&Kp, g_K);
    cudaGetSymbolAddress((void**)&Vp, g_V);
    cudaGetSymbolAddress((void**)&Ap, g_A);

    const int M = BB * SS;  // 8192
    dim3 gemm_grid(DD / 128, M / 128);  // (8, 64)

    gemm_bias_kernel<<<gemm_grid, 256>>>(x, Wq, bq, Qp, M, DD, DD);
    gemm_bias_kernel<<<gemm_grid, 256>>>(x, Wk, bk, Kp, M, DD, DD);
    gemm_bias_kernel<<<gemm_grid, 256>>>(x, Wv, bv, Vp, M, DD, DD);

    rope_kernel<<<(BB * SS * HH * 32) / 256, 256>>>(Qp, Kp);

    attn_kernel<<<dim3(SS / 64, HH, BB), 256>>>(Qp, Kp, Vp, Ap);

    gemm_bias_kernel<<<gemm_grid, 256>>>(Ap, Wo, bo, out, M, DD, DD);
}

// round 3
// speedup vs baseline: 1.6982x; 1.6982x over previous
#include <cuda_runtime.h>
#include <cuda_bf16.h>
#include <cstdint>

// Problem constants
#define BB 4
#define SS 2048
#define DD 1024
#define HH 16
#define HDIM 64
#define MM (BB * SS)   // 8192

// Scratch (allocation-free rule: __device__ globals)
__device__ float g_Q[(size_t)BB * SS * DD];
__device__ float g_K[(size_t)BB * SS * DD];
__device__ float g_V[(size_t)BB * SS * DD];
__device__ float g_A[(size_t)BB * SS * DD];
__device__ float g_cos[SS * 32];
__device__ float g_sin[SS * 32];

// ---------------------------------------------------------------------------
// Helpers (portable PTX only: ldmatrix + mma.sync, sm_80+; no tcgen05)
// ---------------------------------------------------------------------------
__device__ __forceinline__ uint32_t smem_u32(const void* p) {
    uint32_t a;
    asm("{ .reg .u64 t; cvta.to.shared.u64 t, %1; cvt.u32.u64 %0, t; }"
        : "=r"(a) : "l"(p));
    return a;
}

__device__ __forceinline__ void ldsm4(uint32_t* r, uint32_t addr) {
    asm volatile("ldmatrix.sync.aligned.m8n8.x4.shared.b16 {%0,%1,%2,%3}, [%4];"
        : "=r"(r[0]), "=r"(r[1]), "=r"(r[2]), "=r"(r[3]) : "r"(addr));
}

__device__ __forceinline__ void mma_bf16(float* c, const uint32_t* a, const uint32_t* b) {
    asm volatile(
        "mma.sync.aligned.m16n8k16.row.col.f32.bf16.bf16.f32 "
        "{%0,%1,%2,%3}, {%4,%5,%6,%7}, {%8,%9}, {%0,%1,%2,%3};"
        : "+f"(c[0]), "+f"(c[1]), "+f"(c[2]), "+f"(c[3])
        : "r"(a[0]), "r"(a[1]), "r"(a[2]), "r"(a[3]), "r"(b[0]), "r"(b[1]));
}

// fp32 -> bf16 hi + bf16 lo (residual). hi*hi + hi*lo + lo*hi ~ fp32 product.
__device__ __forceinline__ void cvt_split(float4 v, uint2& hi, uint2& lo) {
    uint32_t h01, h23;
    asm("cvt.rn.bf16x2.f32 %0, %1, %2;" : "=r"(h01) : "f"(v.y), "f"(v.x));
    asm("cvt.rn.bf16x2.f32 %0, %1, %2;" : "=r"(h23) : "f"(v.w), "f"(v.z));
    float r0 = v.x - __uint_as_float(h01 << 16);
    float r1 = v.y - __uint_as_float(h01 & 0xffff0000u);
    float r2 = v.z - __uint_as_float(h23 << 16);
    float r3 = v.w - __uint_as_float(h23 & 0xffff0000u);
    uint32_t l01, l23;
    asm("cvt.rn.bf16x2.f32 %0, %1, %2;" : "=r"(l01) : "f"(r1), "f"(r0));
    asm("cvt.rn.bf16x2.f32 %0, %1, %2;" : "=r"(l23) : "f"(r3), "f"(r2));
    hi = make_uint2(h01, h23);
    lo = make_uint2(l01, l23);
}

// ---------------------------------------------------------------------------
// HMMA GEMM: C[M,N] = A[M,K] @ W[N,K]^T + bias[N]  (fp32 in/out)
// 128x128 CTA tile, 8 warps (64x32 each), K-chunk 32, double-buffered smem.
// smem rows padded to 80B so ldmatrix is bank-conflict free.
// Layout per buffer (40960 B): A_hi[128][40h] | A_lo | W_hi | W_lo
// ---------------------------------------------------------------------------
#define GSMEM_TOTAL (2 * 40960)

__global__ __launch_bounds__(256, 1) void gemm_mma_kernel(
    const float* __restrict__ A, const float* __restrict__ W,
    const float* __restrict__ bias, float* __restrict__ C,
    int M, int N, int K)
{
    extern __shared__ char sm[];
    const int tid = threadIdx.x;
    const int wid = tid >> 5, lid = tid & 31;
    const int bm = blockIdx.y * 128, bn = blockIdx.x * 128;
    const int warp_m = wid & 1, warp_n = wid >> 1;
    const int ltx = tid & 7, lty = tid >> 3;   // global loads: 8 x float4 cols, 32 rows

    const uint32_t smb = smem_u32(sm);

    // ldmatrix lane address components
    const int arow = lid & 15;
    const int ak8  = (lid & 16) >> 1;           // 0 or 8 (k-half)
    const int brow = (lid & 7) | ((lid & 16) >> 1);
    const int bk8  = lid & 8;                   // 0 or 8 (k-half)
    const uint32_t aBase = smb + (uint32_t)(warp_m * 64 + arow) * 80 + ak8 * 2;
    const uint32_t bBase = smb + 20480u + (uint32_t)(warp_n * 32 + brow) * 80 + bk8 * 2;

    float acc[4][4][4];
#pragma unroll
    for (int i = 0; i < 4; i++)
#pragma unroll
        for (int j = 0; j < 4; j++)
#pragma unroll
            for (int v = 0; v < 4; v++) acc[i][j][v] = 0.f;

    const float* Ap = A + (size_t)bm * K;
    const float* Wp = W + (size_t)bn * K;

    float4 rA[4], rW[4];
#pragma unroll
    for (int p = 0; p < 4; p++) {
        rA[p] = *(const float4*)(Ap + (size_t)(p * 32 + lty) * K + ltx * 4);
        rW[p] = *(const float4*)(Wp + (size_t)(p * 32 + lty) * K + ltx * 4);
    }

    const int nchunks = K / 32;   // 32
    for (int ck = 0; ck < nchunks; ck++) {
        const int bsel = ck & 1;
        char* buf = sm + bsel * 40960;

        // convert + store current chunk
#pragma unroll
        for (int p = 0; p < 4; p++) {
            int row = p * 32 + lty;
            uint2 h, l;
            cvt_split(rA[p], h, l);
            *(uint2*)(buf + row * 80 + ltx * 8) = h;
            *(uint2*)(buf + 10240 + row * 80 + ltx * 8) = l;
            cvt_split(rW[p], h, l);
            *(uint2*)(buf + 20480 + row * 80 + ltx * 8) = h;
            *(uint2*)(buf + 30720 + row * 80 + ltx * 8) = l;
        }
        __syncthreads();

        // prefetch next chunk (overlaps with MMA below)
        if (ck + 1 < nchunks) {
            const int k0 = (ck + 1) * 32;
#pragma unroll
            for (int p = 0; p < 4; p++) {
                rA[p] = *(const float4*)(Ap + (size_t)(p * 32 + lty) * K + k0 + ltx * 4);
                rW[p] = *(const float4*)(Wp + (size_t)(p * 32 + lty) * K + k0 + ltx * 4);
            }
        }

        const uint32_t bo = (uint32_t)bsel * 40960u;
#pragma unroll
        for (int kk = 0; kk < 2; kk++) {
            uint32_t ah[4][4], alo[4][4], bh[2][4], blo[2][4];
            const uint32_t ka = aBase + bo + kk * 32;
            const uint32_t kb = bBase + bo + kk * 32;
#pragma unroll
            for (int mt = 0; mt < 4; mt++) {
                ldsm4(ah[mt],  ka + mt * 1280);
                ldsm4(alo[mt], ka + 10240 + mt * 1280);
            }
#pragma unroll
            for (int p = 0; p < 2; p++) {
                ldsm4(bh[p],  kb + p * 1280);
                ldsm4(blo[p], kb + 10240 + p * 1280);
            }
#pragma unroll
            for (int mt = 0; mt < 4; mt++)
#pragma unroll
                for (int nt = 0; nt < 4; nt++) {
                    const uint32_t* bhp = &bh[nt >> 1][(nt & 1) * 2];
                    const uint32_t* blp = &blo[nt >> 1][(nt & 1) * 2];
                    mma_bf16(acc[mt][nt], ah[mt], bhp);    // hi*hi
                    mma_bf16(acc[mt][nt], ah[mt], blp);    // hi*lo
                    mma_bf16(acc[mt][nt], alo[mt], bhp);   // lo*hi
                }
        }
    }

    // Epilogue: add bias, store straight from accumulator fragments
    const int gr = lid >> 2, gc = lid & 3;
#pragma unroll
    for (int nt = 0; nt < 4; nt++) {
        const int col = bn + warp_n * 32 + nt * 8 + gc * 2;
        const float2 bv = *(const float2*)(bias + col);
#pragma unroll
        for (int mt = 0; mt < 4; mt++) {
            const int row = bm + warp_m * 64 + mt * 16 + gr;
            float2 o0 = make_float2(acc[mt][nt][0] + bv.x, acc[mt][nt][1] + bv.y);
            float2 o1 = make_float2(acc[mt][nt][2] + bv.x, acc[mt][nt][3] + bv.y);
            *(float2*)(C + (size_t)row * N + col) = o0;
            *(float2*)(C + (size_t)(row + 8) * N + col) = o1;
        }
    }
}

// ---------------------------------------------------------------------------
// RoPE: fp64 table (tiny) + memory-bound apply
// ---------------------------------------------------------------------------
__global__ __launch_bounds__(256) void rope_table_kernel()
{
    int idx = blockIdx.x * 256 + threadIdx.x;   // S*32 = 65536
    int i = idx & 31;
    int s = idx >> 5;
    double inv_freq = exp((double)i * -0.28782313662425575);  // -ln(10000)/32
    double sd, cd;
    sincos((double)s * inv_freq, &sd, &cd);
    g_cos[idx] = (float)cd;
    g_sin[idx] = (float)sd;
}

__global__ __launch_bounds__(256) void rope_apply_kernel(
    float* __restrict__ Qb, float* __restrict__ Kb)
{
    int idx = blockIdx.x * 256 + threadIdx.x;  // over B*S*H*32
    int i = idx & 31;
    int h = (idx >> 5) & (HH - 1);
    int bs = idx >> 9;
    int s = bs & (SS - 1);

    float cs = g_cos[s * 32 + i];
    float sn = g_sin[s * 32 + i];

    size_t off = (size_t)bs * DD + h * HDIM + i;

    float q1 = Qb[off], q2 = Qb[off + 32];
    Qb[off]      = q1 * cs - q2 * sn;
    Qb[off + 32] = q2 * cs + q1 * sn;

    float k1 = Kb[off], k2 = Kb[off + 32];
    Kb[off]      = k1 * cs - k2 * sn;
    Kb[off + 32] = k2 * cs + k1 * sn;
}

// ---------------------------------------------------------------------------
// Causal flash attention (fp32 SIMT). BR=64, BC=32. (Round-3 target: HMMA.)
// ---------------------------------------------------------------------------
__global__ __launch_bounds__(256) void attn_kernel(
    const float* __restrict__ Q, const float* __restrict__ K,
    const float* __restrict__ V, float* __restrict__ O)
{
    const int qt = blockIdx.x;
    const int h  = blockIdx.y;
    const int b  = blockIdx.z;
    const int tid = threadIdx.x;
    const int tx = tid & 15, ty = tid >> 4;

    __shared__ float Qs[64 * 68];
    __shared__ float KP[64 * 34];
    __shared__ float Vs[32 * 64];

    const size_t base = ((size_t)b * SS) * DD + (size_t)h * HDIM;

    for (int t = tid; t < 64 * 64; t += 256) {
        int i = t >> 6, d = t & 63;
        Qs[d * 68 + i] = Q[base + (size_t)(qt * 64 + i) * DD + d] * 0.125f;
    }

    float m_r[4], l_r[4], o_r[4][4];
#pragma unroll
    for (int r = 0; r < 4; r++) {
        m_r[r] = -1e30f;
        l_r[r] = 0.f;
#pragma unroll
        for (int c = 0; c < 4; c++) o_r[r][c] = 0.f;
    }

    const int ntiles = 2 * qt + 2;
    for (int jt = 0; jt < ntiles; ++jt) {
        __syncthreads();

        for (int t = tid; t < 32 * 64; t += 256) {
            int j = t >> 6, d = t & 63;
            KP[d * 34 + j] = K[base + (size_t)(jt * 32 + j) * DD + d];
        }
        for (int t = tid; t < 32 * 16; t += 256) {
            int j = t >> 4, d4 = (t & 15) << 2;
            *(float4*)&Vs[j * 64 + d4] =
                *(const float4*)&V[base + (size_t)(jt * 32 + j) * DD + d4];
        }
        __syncthreads();

        float s00 = 0.f, s01 = 0.f, s10 = 0.f, s11 = 0.f;
        float s20 = 0.f, s21 = 0.f, s30 = 0.f, s31 = 0.f;
#pragma unroll 8
        for (int d = 0; d < 64; ++d) {
            float4 qv = *(const float4*)&Qs[d * 68 + ty * 4];
            float2 kv = *(const float2*)&KP[d * 34 + tx * 2];
            s00 = fmaf(qv.x, kv.x, s00); s01 = fmaf(qv.x, kv.y, s01);
            s10 = fmaf(qv.y, kv.x, s10); s11 = fmaf(qv.y, kv.y, s11);
            s20 = fmaf(qv.z, kv.x, s20); s21 = fmaf(qv.z, kv.y, s21);
            s30 = fmaf(qv.w, kv.x, s30); s31 = fmaf(qv.w, kv.y, s31);
        }
        float s_reg[4][2] = {{s00, s01}, {s10, s11}, {s20, s21}, {s30, s31}};

        if (jt >= 2 * qt) {
            int kbase = jt * 32 + tx * 2;
            int qbase = qt * 64 + ty * 4;
#pragma unroll
            for (int r = 0; r < 4; r++)
#pragma unroll
                for (int c = 0; c < 2; c++)
                    if (kbase + c > qbase + r) s_reg[r][c] = -1e30f;
        }

        float tmax[4];
#pragma unroll
        for (int r = 0; r < 4; r++) tmax[r] = fmaxf(s_reg[r][0], s_reg[r][1]);
#pragma unroll
        for (int o = 8; o > 0; o >>= 1)
#pragma unroll
            for (int r = 0; r < 4; r++)
                tmax[r] = fmaxf(tmax[r], __shfl_xor_sync(0xffffffffu, tmax[r], o, 16));

        float alpha[4], p[4][2], rs[4];
#pragma unroll
        for (int r = 0; r < 4; r++) {
            float nm = fmaxf(m_r[r], tmax[r]);
            alpha[r] = __expf(m_r[r] - nm);
            m_r[r] = nm;
            p[r][0] = __expf(s_reg[r][0] - nm);
            p[r][1] = __expf(s_reg[r][1] - nm);
            rs[r] = p[r][0] + p[r][1];
        }
#pragma unroll
        for (int o = 8; o > 0; o >>= 1)
#pragma unroll
            for (int r = 0; r < 4; r++)
                rs[r] += __shfl_xor_sync(0xffffffffu, rs[r], o, 16);
#pragma unroll
        for (int r = 0; r < 4; r++) {
            l_r[r] = l_r[r] * alpha[r] + rs[r];
#pragma unroll
            for (int c = 0; c < 4; c++) o_r[r][c] *= alpha[r];
        }

        __syncthreads();
#pragma unroll
        for (int r = 0; r < 4; r++)
#pragma unroll
            for (int c = 0; c < 2; c++)
                KP[(tx * 2 + c) * 68 + ty * 4 + r] = p[r][c];
        __syncthreads();

#pragma unroll 8
        for (int j = 0; j < 32; ++j) {
            float4 pv = *(const float4*)&KP[j * 68 + ty * 4];
            float4 vv = *(const float4*)&Vs[j * 64 + tx * 4];
            o_r[0][0] = fmaf(pv.x, vv.x, o_r[0][0]);
            o_r[0][1] = fmaf(pv.x, vv.y, o_r[0][1]);
            o_r[0][2] = fmaf(pv.x, vv.z, o_r[0][2]);
            o_r[0][3] = fmaf(pv.x, vv.w, o_r[0][3]);
            o_r[1][0] = fmaf(pv.y, vv.x, o_r[1][0]);
            o_r[1][1] = fmaf(pv.y, vv.y, o_r[1][1]);
            o_r[1][2] = fmaf(pv.y, vv.z, o_r[1][2]);
            o_r[1][3] = fmaf(pv.y, vv.w, o_r[1][3]);
            o_r[2][0] = fmaf(pv.z, vv.x, o_r[2][0]);
            o_r[2][1] = fmaf(pv.z, vv.y, o_r[2][1]);
            o_r[2][2] = fmaf(pv.z, vv.z, o_r[2][2]);
            o_r[2][3] = fmaf(pv.z, vv.w, o_r[2][3]);
            o_r[3][0] = fmaf(pv.w, vv.x, o_r[3][0]);
            o_r[3][1] = fmaf(pv.w, vv.y, o_r[3][1]);
            o_r[3][2] = fmaf(pv.w, vv.z, o_r[3][2]);
            o_r[3][3] = fmaf(pv.w, vv.w, o_r[3][3]);
        }
    }

#pragma unroll
    for (int r = 0; r < 4; r++) {
        float inv = 1.0f / l_r[r];
        size_t row = base + (size_t)(qt * 64 + ty * 4 + r) * DD + tx * 4;
        float4 v;
        v.x = o_r[r][0] * inv;
        v.y = o_r[r][1] * inv;
        v.z = o_r[r][2] * inv;
        v.w = o_r[r][3] * inv;
        *(float4*)&O[row] = v;
    }
}

// ---------------------------------------------------------------------------
extern "C" void kernel_launch(void* const* d_in, const int* in_sizes, int n_in,
                              void* d_out, int out_size)
{
    (void)in_sizes; (void)n_in; (void)out_size;
    const float* x  = (const float*)d_in[0];
    const float* Wq = (const float*)d_in[1];
    const float* bq = (const float*)d_in[2];
    const float* Wk = (const float*)d_in[3];
    const float* bk = (const float*)d_in[4];
    const float* Wv = (const float*)d_in[5];
    const float* bv = (const float*)d_in[6];
    const float* Wo = (const float*)d_in[7];
    const float* bo = (const float*)d_in[8];
    float* out = (float*)d_out;

    float *Qp, *Kp, *Vp, *Ap;
    cudaGetSymbolAddress((void**)&Qp, g_Q);
    cudaGetSymbolAddress((void**)&Kp, g_K);
    cudaGetSymbolAddress((void**)&Vp, g_V);
    cudaGetSymbolAddress((void**)&Ap, g_A);

    cudaFuncSetAttribute(gemm_mma_kernel,
                         cudaFuncAttributeMaxDynamicSharedMemorySize, GSMEM_TOTAL);

    dim3 gemm_grid(DD / 128, MM / 128);  // (8, 64)

    rope_table_kernel<<<(SS * 32) / 256, 256>>>();

    gemm_mma_kernel<<<gemm_grid, 256, GSMEM_TOTAL>>>(x, Wq, bq, Qp, MM, DD, DD);
    gemm_mma_kernel<<<gemm_grid, 256, GSMEM_TOTAL>>>(x, Wk, bk, Kp, MM, DD, DD);
    gemm_mma_kernel<<<gemm_grid, 256, GSMEM_TOTAL>>>(x, Wv, bv, Vp, MM, DD, DD);

    rope_apply_kernel<<<(BB * SS * HH * 32) / 256, 256>>>(Qp, Kp);

    attn_kernel<<<dim3(SS / 64, HH, BB), 256>>>(Qp, Kp, Vp, Ap);

    gemm_mma_kernel<<<gemm_grid, 256, GSMEM_TOTAL>>>(Ap, Wo, bo, out, MM, DD, DD);
}

// round 4
// speedup vs baseline: 3.0420x; 1.7913x over previous
#include <cuda_runtime.h>
#include <cuda_bf16.h>
#include <cstdint>

// Problem constants
#define BB 4
#define SS 2048
#define DD 1024
#define HH 16
#define HDIM 64
#define MM (BB * SS)   // 8192

// log2(e) * 0.125 (softmax scale folded into Q, exp2 domain)
#define QSC 0.18033688011112042f

// ---------------------------------------------------------------------------
// Device-global scratch (allocation-free rule)
// ---------------------------------------------------------------------------
__device__ float g_Q[(size_t)MM * DD];
__device__ float g_K[(size_t)MM * DD];
__device__ float g_V[(size_t)MM * DD];
__device__ __nv_bfloat16 g_xhi[(size_t)MM * DD], g_xlo[(size_t)MM * DD];
__device__ __nv_bfloat16 g_Wqh[DD * DD], g_Wql[DD * DD];
__device__ __nv_bfloat16 g_Wkh[DD * DD], g_Wkl[DD * DD];
__device__ __nv_bfloat16 g_Wvh[DD * DD], g_Wvl[DD * DD];
__device__ __nv_bfloat16 g_Woh[DD * DD], g_Wol[DD * DD];
__device__ __nv_bfloat16 g_Qhi[(size_t)MM * DD], g_Qlo[(size_t)MM * DD];
__device__ __nv_bfloat16 g_Khi[(size_t)MM * DD], g_Klo[(size_t)MM * DD];
__device__ __nv_bfloat16 g_Vhi[(size_t)MM * DD], g_Vlo[(size_t)MM * DD];
__device__ __nv_bfloat16 g_Ahi[(size_t)MM * DD], g_Alo[(size_t)MM * DD];
__device__ float g_cos[SS * 32];
__device__ float g_sin[SS * 32];

// ---------------------------------------------------------------------------
// PTX helpers (portable sm_80+: ldmatrix, mma.sync, cp.async)
// ---------------------------------------------------------------------------
__device__ __forceinline__ uint32_t smem_u32(const void* p) {
    uint32_t a;
    asm("{ .reg .u64 t; cvta.to.shared.u64 t, %1; cvt.u32.u64 %0, t; }"
        : "=r"(a) : "l"(p));
    return a;
}

__device__ __forceinline__ void ldsm4(uint32_t* r, uint32_t addr) {
    asm volatile("ldmatrix.sync.aligned.m8n8.x4.shared.b16 {%0,%1,%2,%3}, [%4];"
        : "=r"(r[0]), "=r"(r[1]), "=r"(r[2]), "=r"(r[3]) : "r"(addr));
}

__device__ __forceinline__ void ldsm4t(uint32_t* r, uint32_t addr) {
    asm volatile("ldmatrix.sync.aligned.m8n8.x4.trans.shared.b16 {%0,%1,%2,%3}, [%4];"
        : "=r"(r[0]), "=r"(r[1]), "=r"(r[2]), "=r"(r[3]) : "r"(addr));
}

__device__ __forceinline__ void mma_bf16(float* c, const uint32_t* a, const uint32_t* b) {
    asm volatile(
        "mma.sync.aligned.m16n8k16.row.col.f32.bf16.bf16.f32 "
        "{%0,%1,%2,%3}, {%4,%5,%6,%7}, {%8,%9}, {%0,%1,%2,%3};"
        : "+f"(c[0]), "+f"(c[1]), "+f"(c[2]), "+f"(c[3])
        : "r"(a[0]), "r"(a[1]), "r"(a[2]), "r"(a[3]), "r"(b[0]), "r"(b[1]));
}

__device__ __forceinline__ void cp16(uint32_t dst, const void* src) {
    asm volatile("cp.async.cg.shared.global [%0], [%1], 16;" :: "r"(dst), "l"(src));
}
#define CP_COMMIT() asm volatile("cp.async.commit_group;" ::: "memory")
#define CP_WAIT(n)  asm volatile("cp.async.wait_group %0;" :: "n"(n) : "memory")

// fp32 pair -> packed bf16x2 hi + bf16x2 lo (residual)
__device__ __forceinline__ void cvt_split2(float v0, float v1, uint32_t& h, uint32_t& l) {
    asm("cvt.rn.bf16x2.f32 %0, %1, %2;" : "=r"(h) : "f"(v1), "f"(v0));
    float r0 = v0 - __uint_as_float(h << 16);
    float r1 = v1 - __uint_as_float(h & 0xffff0000u);
    asm("cvt.rn.bf16x2.f32 %0, %1, %2;" : "=r"(l) : "f"(r1), "f"(r0));
}

// ---------------------------------------------------------------------------
// Pre-convert: fp32 -> bf16 hi/lo (vectorized, memory-bound)
// ---------------------------------------------------------------------------
__global__ __launch_bounds__(256) void convert_split_kernel(
    const float* __restrict__ src, __nv_bfloat16* __restrict__ hi,
    __nv_bfloat16* __restrict__ lo, int n4)
{
    int i = blockIdx.x * 256 + threadIdx.x;
    if (i >= n4) return;
    float4 v = ((const float4*)src)[i];
    uint32_t h01, h23, l01, l23;
    cvt_split2(v.x, v.y, h01, l01);
    cvt_split2(v.z, v.w, h23, l23);
    ((uint2*)hi)[i] = make_uint2(h01, h23);
    ((uint2*)lo)[i] = make_uint2(l01, l23);
}

// ---------------------------------------------------------------------------
// GEMM: C[M,N] = A[M,K] @ W[N,K]^T + bias.  Inputs pre-split bf16 hi/lo.
// 128x128 CTA, 8 warps (64x32), K-chunk 32, 4-stage cp.async pipeline.
// smem rows padded to 80B (conflict-free ldmatrix, validated in R3).
// Stage layout (40960B): Ahi[128x80] | Alo | Whi | Wlo
// ---------------------------------------------------------------------------
#define GSTAGE 40960
#define GSMEM_TOTAL (4 * GSTAGE)

__global__ __launch_bounds__(256, 1) void gemm_bf16_kernel(
    const __nv_bfloat16* __restrict__ Ahi, const __nv_bfloat16* __restrict__ Alo,
    const __nv_bfloat16* __restrict__ Whi, const __nv_bfloat16* __restrict__ Wlo,
    const float* __restrict__ bias, float* __restrict__ C,
    int M, int N, int K)
{
    extern __shared__ char sm[];
    const uint32_t smb = smem_u32(sm);
    const int tid = threadIdx.x;
    const int wid = tid >> 5, lid = tid & 31;
    const int bm = blockIdx.y * 128, bn = blockIdx.x * 128;
    const int warp_m = wid & 1, warp_n = wid >> 1;

    const __nv_bfloat16* srcs[4] = {
        Ahi + (size_t)bm * K, Alo + (size_t)bm * K,
        Whi + (size_t)bn * K, Wlo + (size_t)bn * K };

    const int arow = lid & 15;
    const int ak16 = (lid & 16);                 // col bytes (k-half * 16B)
    const int brow = (lid & 7) | ((lid & 16) >> 1);
    const int bk16 = (lid & 8) * 2;
    const uint32_t aBase = smb + (uint32_t)(warp_m * 64 + arow) * 80 + ak16;
    const uint32_t bBase = smb + 20480u + (uint32_t)(warp_n * 32 + brow) * 80 + bk16;

    float acc[4][4][4];
#pragma unroll
    for (int i = 0; i < 4; i++)
#pragma unroll
        for (int j = 0; j < 4; j++)
#pragma unroll
            for (int v = 0; v < 4; v++) acc[i][j][v] = 0.f;

    // stage issue: 4 arrays x 128 rows x 4x16B = 2048 cp / 256 thr = 8 each
    auto issue = [&](int ck) {
        const uint32_t base = smb + (uint32_t)(ck & 3) * GSTAGE;
        const int k0 = ck * 32;
#pragma unroll
        for (int a = 0; a < 4; a++) {
#pragma unroll
            for (int i = 0; i < 2; i++) {
                int idx = tid + i * 256;
                int row = idx >> 2, q = idx & 3;
                cp16(base + a * 10240 + row * 80 + q * 16,
                     srcs[a] + (size_t)row * K + k0 + q * 8);
            }
        }
    };

    issue(0); CP_COMMIT();
    issue(1); CP_COMMIT();
    issue(2); CP_COMMIT();

    const int nchunks = K / 32;
    for (int ck = 0; ck < nchunks; ck++) {
        CP_WAIT(2);
        __syncthreads();
        if (ck + 3 < nchunks) issue(ck + 3);
        CP_COMMIT();

        const uint32_t bo = (uint32_t)(ck & 3) * GSTAGE;
#pragma unroll
        for (int kk = 0; kk < 2; kk++) {
            uint32_t ah[4][4], alo[4][4], bh[2][4], blo[2][4];
            const uint32_t ka = aBase + bo + kk * 32;
            const uint32_t kb = bBase + bo + kk * 32;
#pragma unroll
            for (int mt = 0; mt < 4; mt++) {
                ldsm4(ah[mt],  ka + mt * 1280);
                ldsm4(alo[mt], ka + 10240 + mt * 1280);
            }
#pragma unroll
            for (int p = 0; p < 2; p++) {
                ldsm4(bh[p],  kb + p * 1280);
                ldsm4(blo[p], kb + 10240 + p * 1280);
            }
#pragma unroll
            for (int mt = 0; mt < 4; mt++)
#pragma unroll
                for (int nt = 0; nt < 4; nt++) {
                    const uint32_t* bhp = &bh[nt >> 1][(nt & 1) * 2];
                    const uint32_t* blp = &blo[nt >> 1][(nt & 1) * 2];
                    mma_bf16(acc[mt][nt], ah[mt], bhp);    // hi*hi
                    mma_bf16(acc[mt][nt], ah[mt], blp);    // hi*lo
                    mma_bf16(acc[mt][nt], alo[mt], bhp);   // lo*hi
                }
        }
    }

    const int gr = lid >> 2, gc = lid & 3;
#pragma unroll
    for (int nt = 0; nt < 4; nt++) {
        const int col = bn + warp_n * 32 + nt * 8 + gc * 2;
        const float2 bv = *(const float2*)(bias + col);
#pragma unroll
        for (int mt = 0; mt < 4; mt++) {
            const int row = bm + warp_m * 64 + mt * 16 + gr;
            *(float2*)(C + (size_t)row * N + col) =
                make_float2(acc[mt][nt][0] + bv.x, acc[mt][nt][1] + bv.y);
            *(float2*)(C + (size_t)(row + 8) * N + col) =
                make_float2(acc[mt][nt][2] + bv.x, acc[mt][nt][3] + bv.y);
        }
    }
}

// ---------------------------------------------------------------------------
// RoPE tables (fp64 phase, immune to fast-math) + fused rotate/scale/split
// ---------------------------------------------------------------------------
__global__ __launch_bounds__(256) void rope_table_kernel()
{
    int idx = blockIdx.x * 256 + threadIdx.x;   // S*32
    int i = idx & 31;
    int s = idx >> 5;
    double inv_freq = exp((double)i * -0.28782313662425575);  // -ln(10000)/32
    double sd, cd;
    sincos((double)s * inv_freq, &sd, &cd);
    g_cos[idx] = (float)cd;
    g_sin[idx] = (float)sd;
}

// Reads fp32 Q/K (GEMM out), rotates, writes bf16 hi/lo. Q gets exp2-domain scale.
__global__ __launch_bounds__(256) void rope_split_kernel()
{
    int idx = blockIdx.x * 256 + threadIdx.x;  // B*S*H*32
    int i = idx & 31;
    int h = (idx >> 5) & (HH - 1);
    int bs = idx >> 9;
    int s = bs & (SS - 1);

    float cs = g_cos[s * 32 + i];
    float sn = g_sin[s * 32 + i];
    size_t off = (size_t)bs * DD + h * HDIM + i;

    float q1 = g_Q[off], q2 = g_Q[off + 32];
    float q1r = (q1 * cs - q2 * sn) * QSC;
    float q2r = (q2 * cs + q1 * sn) * QSC;
    __nv_bfloat16 h1 = __float2bfloat16(q1r);
    __nv_bfloat16 h2 = __float2bfloat16(q2r);
    g_Qhi[off] = h1;      g_Qlo[off] = __float2bfloat16(q1r - __bfloat162float(h1));
    g_Qhi[off + 32] = h2; g_Qlo[off + 32] = __float2bfloat16(q2r - __bfloat162float(h2));

    float k1 = g_K[off], k2 = g_K[off + 32];
    float k1r = k1 * cs - k2 * sn;
    float k2r = k2 * cs + k1 * sn;
    h1 = __float2bfloat16(k1r);
    h2 = __float2bfloat16(k2r);
    g_Khi[off] = h1;      g_Klo[off] = __float2bfloat16(k1r - __bfloat162float(h1));
    g_Khi[off + 32] = h2; g_Klo[off + 32] = __float2bfloat16(k2r - __bfloat162float(h2));
}

// ---------------------------------------------------------------------------
// HMMA causal flash attention. BR=128 (8 warps x 16 rows), BC=64, HD=64.
// S = QK^T and O += PV both 3-term bf16-split (near-fp32). Online softmax
// in exp2 domain (scale folded into Q). P never leaves registers.
// smem: Qhi/Qlo [128x144B] + 2 stages x {Khi,Klo,Vhi,Vlo}[64x144B] = 108 KB
// ---------------------------------------------------------------------------
#define AQ_B   18432            // 128*144
#define AARR_B 9216             // 64*144
#define ASTG_B (4 * AARR_B)     // 36864
#define ASMEM_TOTAL (2 * AQ_B + 2 * ASTG_B)   // 110592

__global__ __launch_bounds__(256, 1) void attn_mma_kernel()
{
    extern __shared__ char sm[];
    const uint32_t smb = smem_u32(sm);
    const int tid = threadIdx.x;
    const int w = tid >> 5, lane = tid & 31;
    const int gr = lane >> 2, gc = lane & 3;
    const int qt = (int)gridDim.x - 1 - (int)blockIdx.x;   // long blocks first
    const int h = blockIdx.y, b = blockIdx.z;

    const size_t hb = ((size_t)b * SS) * DD + (size_t)h * HDIM;
    const size_t qrow0 = (size_t)qt * 128;

    // --- prologue: Q tile (hi+lo), one group ---
    {
        const __nv_bfloat16* qs[2] = { g_Qhi, g_Qlo };
#pragma unroll
        for (int a = 0; a < 2; a++)
#pragma unroll
            for (int i = 0; i < 4; i++) {
                int idx = tid + i * 256;           // 1024 chunks / array
                int row = idx >> 3, c = idx & 7;
                cp16(smb + a * AQ_B + row * 144 + c * 16,
                     qs[a] + hb + (qrow0 + row) * DD + c * 8);
            }
        CP_COMMIT();
    }

    auto stage_load = [&](int jt, int s) {
        const __nv_bfloat16* ks[4] = { g_Khi, g_Klo, g_Vhi, g_Vlo };
        const uint32_t base = smb + 2 * AQ_B + (uint32_t)s * ASTG_B;
#pragma unroll
        for (int a = 0; a < 4; a++)
#pragma unroll
            for (int i = 0; i < 2; i++) {
                int idx = tid + i * 256;           // 512 chunks / array
                int row = idx >> 3, c = idx & 7;
                cp16(base + a * AARR_B + row * 144 + c * 16,
                     ks[a] + hb + (size_t)(jt * 64 + row) * DD + c * 8);
            }
    };
    stage_load(0, 0); CP_COMMIT();

    float m0 = -1e30f, m1 = -1e30f, l0 = 0.f, l1 = 0.f;
    float o[8][4];
#pragma unroll
    for (int d = 0; d < 8; d++)
#pragma unroll
        for (int v = 0; v < 4; v++) o[d][v] = 0.f;

    uint32_t aQh[4][4], aQl[4][4];

    const int qrow_lo = qt * 128 + w * 16 + gr;   // row of c-regs {0,1}
    const int ntiles = 2 * qt + 2;

    for (int jt = 0; jt < ntiles; jt++) {
        CP_WAIT(0);
        __syncthreads();
        if (jt + 1 < ntiles) stage_load(jt + 1, (jt + 1) & 1);
        CP_COMMIT();

        if (jt == 0) {   // Q fragments (loop-invariant)
            const uint32_t qa = smb + (uint32_t)(w * 16 + (lane & 15)) * 144
                                + (lane >> 4) * 16;
#pragma unroll
            for (int kt = 0; kt < 4; kt++) {
                ldsm4(aQh[kt], qa + kt * 32);
                ldsm4(aQl[kt], qa + AQ_B + kt * 32);
            }
        }

        const uint32_t stg = smb + 2 * AQ_B + (uint32_t)(jt & 1) * ASTG_B;

        // ---- S = Q K^T (3-term split) ----
        float sc[8][4];
#pragma unroll
        for (int nt = 0; nt < 8; nt++)
#pragma unroll
            for (int v = 0; v < 4; v++) sc[nt][v] = 0.f;

        const uint32_t kaddr = stg
            + (uint32_t)((lane & 7) | ((lane & 16) >> 1)) * 144 + (lane & 8) * 2;
#pragma unroll
        for (int kt = 0; kt < 4; kt++) {
            uint32_t bKh[4][4], bKl[4][4];
#pragma unroll
            for (int np = 0; np < 4; np++) {
                ldsm4(bKh[np], kaddr + np * 2304 + kt * 32);
                ldsm4(bKl[np], kaddr + AARR_B + np * 2304 + kt * 32);
            }
#pragma unroll
            for (int np = 0; np < 4; np++) {
                mma_bf16(sc[2*np],   aQh[kt], &bKh[np][0]);
                mma_bf16(sc[2*np+1], aQh[kt], &bKh[np][2]);
                mma_bf16(sc[2*np],   aQh[kt], &bKl[np][0]);
                mma_bf16(sc[2*np+1], aQh[kt], &bKl[np][2]);
                mma_bf16(sc[2*np],   aQl[kt], &bKh[np][0]);
                mma_bf16(sc[2*np+1], aQl[kt], &bKh[np][2]);
            }
        }

        // ---- causal mask (only last two tiles) ----
        if (jt >= 2 * qt) {
#pragma unroll
            for (int nt = 0; nt < 8; nt++) {
                int j = jt * 64 + nt * 8 + gc * 2;
                if (j     > qrow_lo)     sc[nt][0] = -1e30f;
                if (j + 1 > qrow_lo)     sc[nt][1] = -1e30f;
                if (j     > qrow_lo + 8) sc[nt][2] = -1e30f;
                if (j + 1 > qrow_lo + 8) sc[nt][3] = -1e30f;
            }
        }

        // ---- online softmax (exp2 domain) ----
        float mx0 = -1e30f, mx1 = -1e30f;
#pragma unroll
        for (int nt = 0; nt < 8; nt++) {
            mx0 = fmaxf(mx0, fmaxf(sc[nt][0], sc[nt][1]));
            mx1 = fmaxf(mx1, fmaxf(sc[nt][2], sc[nt][3]));
        }
        mx0 = fmaxf(mx0, __shfl_xor_sync(0xffffffffu, mx0, 1));
        mx0 = fmaxf(mx0, __shfl_xor_sync(0xffffffffu, mx0, 2));
        mx1 = fmaxf(mx1, __shfl_xor_sync(0xffffffffu, mx1, 1));
        mx1 = fmaxf(mx1, __shfl_xor_sync(0xffffffffu, mx1, 2));

        float mn0 = fmaxf(m0, mx0), mn1 = fmaxf(m1, mx1);
        float al0 = exp2f(m0 - mn0), al1 = exp2f(m1 - mn1);
        m0 = mn0; m1 = mn1;

        float rs0 = 0.f, rs1 = 0.f;
#pragma unroll
        for (int nt = 0; nt < 8; nt++) {
            sc[nt][0] = exp2f(sc[nt][0] - mn0);
            sc[nt][1] = exp2f(sc[nt][1] - mn0);
            sc[nt][2] = exp2f(sc[nt][2] - mn1);
            sc[nt][3] = exp2f(sc[nt][3] - mn1);
            rs0 += sc[nt][0] + sc[nt][1];
            rs1 += sc[nt][2] + sc[nt][3];
        }
        rs0 += __shfl_xor_sync(0xffffffffu, rs0, 1);
        rs0 += __shfl_xor_sync(0xffffffffu, rs0, 2);
        rs1 += __shfl_xor_sync(0xffffffffu, rs1, 1);
        rs1 += __shfl_xor_sync(0xffffffffu, rs1, 2);
        l0 = l0 * al0 + rs0;
        l1 = l1 * al1 + rs1;
#pragma unroll
        for (int d = 0; d < 8; d++) {
            o[d][0] *= al0; o[d][1] *= al0;
            o[d][2] *= al1; o[d][3] *= al1;
        }

        // ---- O += P V (3-term split; P stays in registers) ----
        const uint32_t vaddr = stg + 2 * AARR_B
            + (uint32_t)(lane & 15) * 144 + (lane >> 4) * 16;
#pragma unroll
        for (int kt = 0; kt < 4; kt++) {
            uint32_t aPh[4], aPl[4];
            cvt_split2(sc[2*kt][0],   sc[2*kt][1],   aPh[0], aPl[0]);
            cvt_split2(sc[2*kt][2],   sc[2*kt][3],   aPh[1], aPl[1]);
            cvt_split2(sc[2*kt+1][0], sc[2*kt+1][1], aPh[2], aPl[2]);
            cvt_split2(sc[2*kt+1][2], sc[2*kt+1][3], aPh[3], aPl[3]);

            uint32_t bVh[4][4], bVl[4][4];
#pragma unroll
            for (int dp = 0; dp < 4; dp++) {
                ldsm4t(bVh[dp], vaddr + kt * 2304 + dp * 32);
                ldsm4t(bVl[dp], vaddr + AARR_B + kt * 2304 + dp * 32);
            }
#pragma unroll
            for (int dp = 0; dp < 4; dp++) {
                mma_bf16(o[2*dp],   aPh, &bVh[dp][0]);
                mma_bf16(o[2*dp+1], aPh, &bVh[dp][2]);
                mma_bf16(o[2*dp],   aPh, &bVl[dp][0]);
                mma_bf16(o[2*dp+1], aPh, &bVl[dp][2]);
                mma_bf16(o[2*dp],   aPl, &bVh[dp][0]);
                mma_bf16(o[2*dp+1], aPl, &bVh[dp][2]);
            }
        }
    }

    // ---- epilogue: /l, split to bf16 hi/lo, write merged [B,S,D] ----
    const float inv0 = 1.0f / l0, inv1 = 1.0f / l1;
#pragma unroll
    for (int dt = 0; dt < 8; dt++) {
        size_t idx = hb + (qrow0 + w * 16 + gr) * DD + dt * 8 + gc * 2;
        uint32_t hh, ll;
        cvt_split2(o[dt][0] * inv0, o[dt][1] * inv0, hh, ll);
        *(uint32_t*)&g_Ahi[idx] = hh;
        *(uint32_t*)&g_Alo[idx] = ll;
        size_t idx8 = idx + 8 * DD;
        cvt_split2(o[dt][2] * inv1, o[dt][3] * inv1, hh, ll);
        *(uint32_t*)&g_Ahi[idx8] = hh;
        *(uint32_t*)&g_Alo[idx8] = ll;
    }
}

// ---------------------------------------------------------------------------
extern "C" void kernel_launch(void* const* d_in, const int* in_sizes, int n_in,
                              void* d_out, int out_size)
{
    (void)in_sizes; (void)n_in; (void)out_size;
    const float* x  = (const float*)d_in[0];
    const float* Wq = (const float*)d_in[1];
    const float* bq = (const float*)d_in[2];
    const float* Wk = (const float*)d_in[3];
    const float* bk = (const float*)d_in[4];
    const float* Wv = (const float*)d_in[5];
    const float* bv = (const float*)d_in[6];
    const float* Wo = (const float*)d_in[7];
    const float* bo = (const float*)d_in[8];
    float* out = (float*)d_out;

    float *Qp, *Kp, *Vp;
    __nv_bfloat16 *xh, *xl, *wqh, *wql, *wkh, *wkl, *wvh, *wvl, *woh, *wol;
    __nv_bfloat16 *vh, *vl, *ah, *al;
    cudaGetSymbolAddress((void**)&Qp, g_Q);
    cudaGetSymbolAddress((void**)&Kp, g_K);
    cudaGetSymbolAddress((void**)&Vp, g_V);
    cudaGetSymbolAddress((void**)&xh, g_xhi);
    cudaGetSymbolAddress((void**)&xl, g_xlo);
    cudaGetSymbolAddress((void**)&wqh, g_Wqh);
    cudaGetSymbolAddress((void**)&wql, g_Wql);
    cudaGetSymbolAddress((void**)&wkh, g_Wkh);
    cudaGetSymbolAddress((void**)&wkl, g_Wkl);
    cudaGetSymbolAddress((void**)&wvh, g_Wvh);
    cudaGetSymbolAddress((void**)&wvl, g_Wvl);
    cudaGetSymbolAddress((void**)&woh, g_Woh);
    cudaGetSymbolAddress((void**)&wol, g_Wol);
    cudaGetSymbolAddress((void**)&vh, g_Vhi);
    cudaGetSymbolAddress((void**)&vl, g_Vlo);
    cudaGetSymbolAddress((void**)&ah, g_Ahi);
    cudaGetSymbolAddress((void**)&al, g_Alo);

    cudaFuncSetAttribute(gemm_bf16_kernel,
                         cudaFuncAttributeMaxDynamicSharedMemorySize, GSMEM_TOTAL);
    cudaFuncSetAttribute(attn_mma_kernel,
                         cudaFuncAttributeMaxDynamicSharedMemorySize, ASMEM_TOTAL);

    const int NX4 = MM * DD / 4;   // 2097152
    const int NW4 = DD * DD / 4;   // 262144

    rope_table_kernel<<<(SS * 32) / 256, 256>>>();
    convert_split_kernel<<<NX4 / 256, 256>>>(x,  xh,  xl,  NX4);
    convert_split_kernel<<<NW4 / 256, 256>>>(Wq, wqh, wql, NW4);
    convert_split_kernel<<<NW4 / 256, 256>>>(Wk, wkh, wkl, NW4);
    convert_split_kernel<<<NW4 / 256, 256>>>(Wv, wvh, wvl, NW4);
    convert_split_kernel<<<NW4 / 256, 256>>>(Wo, woh, wol, NW4);

    dim3 gemm_grid(DD / 128, MM / 128);  // (8, 64)
    gemm_bf16_kernel<<<gemm_grid, 256, GSMEM_TOTAL>>>(xh, xl, wqh, wql, bq, Qp, MM, DD, DD);
    gemm_bf16_kernel<<<gemm_grid, 256, GSMEM_TOTAL>>>(xh, xl, wkh, wkl, bk, Kp, MM, DD, DD);
    gemm_bf16_kernel<<<gemm_grid, 256, GSMEM_TOTAL>>>(xh, xl, wvh, wvl, bv, Vp, MM, DD, DD);

    rope_split_kernel<<<(BB * SS * HH * 32) / 256, 256>>>();
    convert_split_kernel<<<NX4 / 256, 256>>>(Vp, vh, vl, NX4);

    attn_mma_kernel<<<dim3(SS / 128, HH, BB), 256, ASMEM_TOTAL>>>();

    gemm_bf16_kernel<<<gemm_grid, 256, GSMEM_TOTAL>>>(ah, al, woh, wol, bo, out, MM, DD, DD);
}

// round 5
// speedup vs baseline: 3.3910x; 1.1147x over previous
#include <cuda_runtime.h>
#include <cuda_bf16.h>
#include <cuda_fp16.h>
#include <cstdint>

// Problem constants
#define BB 4
#define SS 2048
#define DD 1024
#define HH 16
#define HDIM 64
#define MM (BB * SS)   // 8192

// log2(e) * 0.125 (softmax scale folded into Q, exp2 domain)
#define QSC 0.18033688011112042f

// ---------------------------------------------------------------------------
// Device-global scratch (allocation-free rule)
// ---------------------------------------------------------------------------
__device__ __nv_bfloat16 g_xhi[(size_t)MM * DD], g_xlo[(size_t)MM * DD];
__device__ __nv_bfloat16 g_Wqh[DD * DD], g_Wql[DD * DD];
__device__ __nv_bfloat16 g_Wkh[DD * DD], g_Wkl[DD * DD];
__device__ __nv_bfloat16 g_Wvh[DD * DD], g_Wvl[DD * DD];
__device__ __nv_bfloat16 g_Woh[DD * DD], g_Wol[DD * DD];
__device__ __half g_Qh[(size_t)MM * DD];                       // single fp16 (scaled)
__device__ __half g_Khi[(size_t)MM * DD], g_Klo[(size_t)MM * DD];
__device__ __half g_Vhi[(size_t)MM * DD], g_Vlo[(size_t)MM * DD];
__device__ __nv_bfloat16 g_Ahi[(size_t)MM * DD], g_Alo[(size_t)MM * DD];
__device__ float g_cos[SS * 32];
__device__ float g_sin[SS * 32];

// ---------------------------------------------------------------------------
// PTX helpers (portable sm_80+: ldmatrix, mma.sync, cp.async)
// ---------------------------------------------------------------------------
__device__ __forceinline__ uint32_t smem_u32(const void* p) {
    uint32_t a;
    asm("{ .reg .u64 t; cvta.to.shared.u64 t, %1; cvt.u32.u64 %0, t; }"
        : "=r"(a) : "l"(p));
    return a;
}

__device__ __forceinline__ void ldsm4(uint32_t* r, uint32_t addr) {
    asm volatile("ldmatrix.sync.aligned.m8n8.x4.shared.b16 {%0,%1,%2,%3}, [%4];"
        : "=r"(r[0]), "=r"(r[1]), "=r"(r[2]), "=r"(r[3]) : "r"(addr));
}

__device__ __forceinline__ void ldsm4t(uint32_t* r, uint32_t addr) {
    asm volatile("ldmatrix.sync.aligned.m8n8.x4.trans.shared.b16 {%0,%1,%2,%3}, [%4];"
        : "=r"(r[0]), "=r"(r[1]), "=r"(r[2]), "=r"(r[3]) : "r"(addr));
}

__device__ __forceinline__ void mma_bf16(float* c, const uint32_t* a, const uint32_t* b) {
    asm volatile(
        "mma.sync.aligned.m16n8k16.row.col.f32.bf16.bf16.f32 "
        "{%0,%1,%2,%3}, {%4,%5,%6,%7}, {%8,%9}, {%0,%1,%2,%3};"
        : "+f"(c[0]), "+f"(c[1]), "+f"(c[2]), "+f"(c[3])
        : "r"(a[0]), "r"(a[1]), "r"(a[2]), "r"(a[3]), "r"(b[0]), "r"(b[1]));
}

__device__ __forceinline__ void mma_f16(float* c, const uint32_t* a, const uint32_t* b) {
    asm volatile(
        "mma.sync.aligned.m16n8k16.row.col.f32.f16.f16.f32 "
        "{%0,%1,%2,%3}, {%4,%5,%6,%7}, {%8,%9}, {%0,%1,%2,%3};"
        : "+f"(c[0]), "+f"(c[1]), "+f"(c[2]), "+f"(c[3])
        : "r"(a[0]), "r"(a[1]), "r"(a[2]), "r"(a[3]), "r"(b[0]), "r"(b[1]));
}

__device__ __forceinline__ void cp16(uint32_t dst, const void* src) {
    asm volatile("cp.async.cg.shared.global [%0], [%1], 16;" :: "r"(dst), "l"(src));
}
#define CP_COMMIT() asm volatile("cp.async.commit_group;" ::: "memory")
#define CP_WAIT(n)  asm volatile("cp.async.wait_group %0;" :: "n"(n) : "memory")

// fp32 pair -> packed bf16x2 hi + bf16x2 lo (residual)
__device__ __forceinline__ void cvt_split2(float v0, float v1, uint32_t& h, uint32_t& l) {
    asm("cvt.rn.bf16x2.f32 %0, %1, %2;" : "=r"(h) : "f"(v1), "f"(v0));
    float r0 = v0 - __uint_as_float(h << 16);
    float r1 = v1 - __uint_as_float(h & 0xffff0000u);
    asm("cvt.rn.bf16x2.f32 %0, %1, %2;" : "=r"(l) : "f"(r1), "f"(r0));
}

// fp32 pair -> packed f16x2 (lo half = v0)
__device__ __forceinline__ uint32_t pack_f16(float v0, float v1) {
    uint32_t r;
    asm("cvt.rn.f16x2.f32 %0, %1, %2;" : "=r"(r) : "f"(v1), "f"(v0));
    return r;
}

// fp32 pair -> f16x2 hi + f16x2 lo (residual)
__device__ __forceinline__ void split_f16(float v0, float v1, uint32_t& h, uint32_t& l) {
    h = pack_f16(v0, v1);
    float f0, f1;
    asm("{.reg .b16 a,b;\n\t mov.b32 {a,b}, %2;\n\t"
        "cvt.f32.f16 %0, a;\n\t cvt.f32.f16 %1, b;}"
        : "=f"(f0), "=f"(f1) : "r"(h));
    l = pack_f16(v0 - f0, v1 - f1);
}

// ---------------------------------------------------------------------------
// Pre-convert: fp32 -> bf16 hi/lo (x and weights)
// ---------------------------------------------------------------------------
__global__ __launch_bounds__(256) void convert_split_kernel(
    const float* __restrict__ src, __nv_bfloat16* __restrict__ hi,
    __nv_bfloat16* __restrict__ lo, int n4)
{
    int i = blockIdx.x * 256 + threadIdx.x;
    if (i >= n4) return;
    float4 v = ((const float4*)src)[i];
    uint32_t h01, h23, l01, l23;
    cvt_split2(v.x, v.y, h01, l01);
    cvt_split2(v.z, v.w, h23, l23);
    ((uint2*)hi)[i] = make_uint2(h01, h23);
    ((uint2*)lo)[i] = make_uint2(l01, l23);
}

// ---------------------------------------------------------------------------
// RoPE tables (fp64 phase, immune to fast-math)
// ---------------------------------------------------------------------------
__global__ __launch_bounds__(256) void rope_table_kernel()
{
    int idx = blockIdx.x * 256 + threadIdx.x;   // S*32
    int i = idx & 31;
    int s = idx >> 5;
    double inv_freq = exp((double)i * -0.28782313662425575);  // -ln(10000)/32
    double sd, cd;
    sincos((double)s * inv_freq, &sd, &cd);
    g_cos[idx] = (float)cd;
    g_sin[idx] = (float)sd;
}

// ---------------------------------------------------------------------------
// Fused QKV GEMM (bf16 3-term, near-fp32): z = 0:Q, 1:K, 2:V.
// 128x128 CTA, 8 warps (64x32), K-chunk 32, 4-stage cp.async pipeline.
// Epilogue: z<2 -> smem-staged RoPE + fp16 store (Q single / K hi+lo);
//           z=2 -> direct fp16 hi/lo split store.
// ---------------------------------------------------------------------------
#define GSTAGE 40960
#define GSMEM_TOTAL (4 * GSTAGE)

__global__ __launch_bounds__(256, 1) void gemm_qkv_kernel(
    const __nv_bfloat16* __restrict__ xh, const __nv_bfloat16* __restrict__ xl,
    const __nv_bfloat16* __restrict__ Wqh, const __nv_bfloat16* __restrict__ Wql,
    const __nv_bfloat16* __restrict__ Wkh, const __nv_bfloat16* __restrict__ Wkl,
    const __nv_bfloat16* __restrict__ Wvh, const __nv_bfloat16* __restrict__ Wvl,
    const float* __restrict__ bq, const float* __restrict__ bk,
    const float* __restrict__ bv)
{
    extern __shared__ char sm[];
    const uint32_t smb = smem_u32(sm);
    const int tid = threadIdx.x;
    const int wid = tid >> 5, lid = tid & 31;
    const int bm = blockIdx.y * 128, bn = blockIdx.x * 128;
    const int z = blockIdx.z;
    const int warp_m = wid & 1, warp_n = wid >> 1;

    const __nv_bfloat16* Whi = (z == 0) ? Wqh : (z == 1) ? Wkh : Wvh;
    const __nv_bfloat16* Wlo = (z == 0) ? Wql : (z == 1) ? Wkl : Wvl;
    const float* bias = (z == 0) ? bq : (z == 1) ? bk : bv;

    const __nv_bfloat16* srcs[4] = {
        xh + (size_t)bm * DD, xl + (size_t)bm * DD,
        Whi + (size_t)bn * DD, Wlo + (size_t)bn * DD };

    const int arow = lid & 15;
    const int ak16 = (lid & 16);
    const int brow = (lid & 7) | ((lid & 16) >> 1);
    const int bk16 = (lid & 8) * 2;
    const uint32_t aBase = smb + (uint32_t)(warp_m * 64 + arow) * 80 + ak16;
    const uint32_t bBase = smb + 20480u + (uint32_t)(warp_n * 32 + brow) * 80 + bk16;

    float acc[4][4][4];
#pragma unroll
    for (int i = 0; i < 4; i++)
#pragma unroll
        for (int j = 0; j < 4; j++)
#pragma unroll
            for (int v = 0; v < 4; v++) acc[i][j][v] = 0.f;

    auto issue = [&](int ck) {
        const uint32_t base = smb + (uint32_t)(ck & 3) * GSTAGE;
        const int k0 = ck * 32;
#pragma unroll
        for (int a = 0; a < 4; a++) {
#pragma unroll
            for (int i = 0; i < 2; i++) {
                int idx = tid + i * 256;
                int row = idx >> 2, q = idx & 3;
                cp16(base + a * 10240 + row * 80 + q * 16,
                     srcs[a] + (size_t)row * DD + k0 + q * 8);
            }
        }
    };

    issue(0); CP_COMMIT();
    issue(1); CP_COMMIT();
    issue(2); CP_COMMIT();

    const int nchunks = DD / 32;
    for (int ck = 0; ck < nchunks; ck++) {
        CP_WAIT(2);
        __syncthreads();
        if (ck + 3 < nchunks) issue(ck + 3);
        CP_COMMIT();

        const uint32_t bo = (uint32_t)(ck & 3) * GSTAGE;
#pragma unroll
        for (int kk = 0; kk < 2; kk++) {
            uint32_t ah[4][4], alo[4][4], bh[2][4], blo[2][4];
            const uint32_t ka = aBase + bo + kk * 32;
            const uint32_t kb = bBase + bo + kk * 32;
#pragma unroll
            for (int mt = 0; mt < 4; mt++) {
                ldsm4(ah[mt],  ka + mt * 1280);
                ldsm4(alo[mt], ka + 10240 + mt * 1280);
            }
#pragma unroll
            for (int p = 0; p < 2; p++) {
                ldsm4(bh[p],  kb + p * 1280);
                ldsm4(blo[p], kb + 10240 + p * 1280);
            }
#pragma unroll
            for (int mt = 0; mt < 4; mt++)
#pragma unroll
                for (int nt = 0; nt < 4; nt++) {
                    const uint32_t* bhp = &bh[nt >> 1][(nt & 1) * 2];
                    const uint32_t* blp = &blo[nt >> 1][(nt & 1) * 2];
                    mma_bf16(acc[mt][nt], ah[mt], bhp);
                    mma_bf16(acc[mt][nt], ah[mt], blp);
                    mma_bf16(acc[mt][nt], alo[mt], bhp);
                }
        }
    }

    const int gr = lid >> 2, gc = lid & 3;

    if (z == 2) {
        // V: direct fp16 hi/lo split (+bias)
#pragma unroll
        for (int nt = 0; nt < 4; nt++) {
            const int col = bn + warp_n * 32 + nt * 8 + gc * 2;
            const float2 bv2 = *(const float2*)(bias + col);
#pragma unroll
            for (int mt = 0; mt < 4; mt++) {
                const int row = bm + warp_m * 64 + mt * 16 + gr;
                uint32_t h, l;
                split_f16(acc[mt][nt][0] + bv2.x, acc[mt][nt][1] + bv2.y, h, l);
                *(uint32_t*)&g_Vhi[(size_t)row * DD + col] = h;
                *(uint32_t*)&g_Vlo[(size_t)row * DD + col] = l;
                split_f16(acc[mt][nt][2] + bv2.x, acc[mt][nt][3] + bv2.y, h, l);
                *(uint32_t*)&g_Vhi[(size_t)(row + 8) * DD + col] = h;
                *(uint32_t*)&g_Vlo[(size_t)(row + 8) * DD + col] = l;
            }
        }
        return;
    }

    // Q/K: stage to smem (+bias), then RoPE across (i, i+32) pairs.
    CP_WAIT(0);
    __syncthreads();
    float* Ds = (float*)sm;    // [128][132]
#pragma unroll
    for (int nt = 0; nt < 4; nt++) {
        const int cl = warp_n * 32 + nt * 8 + gc * 2;
        const float2 bv2 = *(const float2*)(bias + bn + cl);
#pragma unroll
        for (int mt = 0; mt < 4; mt++) {
            const int rl = warp_m * 64 + mt * 16 + gr;
            Ds[rl * 132 + cl]     = acc[mt][nt][0] + bv2.x;
            Ds[rl * 132 + cl + 1] = acc[mt][nt][1] + bv2.y;
            Ds[(rl + 8) * 132 + cl]     = acc[mt][nt][2] + bv2.x;
            Ds[(rl + 8) * 132 + cl + 1] = acc[mt][nt][3] + bv2.y;
        }
    }
    __syncthreads();

    for (int u = tid; u < 128 * 32; u += 256) {
        const int row = u >> 5, t = u & 31;
        const int hl = t >> 4, tt = t & 15;
        const int col = hl * 64 + tt * 2;
        const int s = (bm + row) & (SS - 1);
        const int i0 = tt * 2;
        const float cs0 = g_cos[s * 32 + i0], sn0 = g_sin[s * 32 + i0];
        const float cs1 = g_cos[s * 32 + i0 + 1], sn1 = g_sin[s * 32 + i0 + 1];
        const float v1a = Ds[row * 132 + col],      v1b = Ds[row * 132 + col + 1];
        const float v2a = Ds[row * 132 + col + 32], v2b = Ds[row * 132 + col + 33];
        const float r1a = v1a * cs0 - v2a * sn0, r2a = v2a * cs0 + v1a * sn0;
        const float r1b = v1b * cs1 - v2b * sn1, r2b = v2b * cs1 + v1b * sn1;
        const size_t out = (size_t)(bm + row) * DD + bn + col;
        if (z == 0) {
            *(uint32_t*)&g_Qh[out]      = pack_f16(r1a * QSC, r1b * QSC);
            *(uint32_t*)&g_Qh[out + 32] = pack_f16(r2a * QSC, r2b * QSC);
        } else {
            uint32_t h, l;
            split_f16(r1a, r1b, h, l);
            *(uint32_t*)&g_Khi[out] = h; *(uint32_t*)&g_Klo[out] = l;
            split_f16(r2a, r2b, h, l);
            *(uint32_t*)&g_Khi[out + 32] = h; *(uint32_t*)&g_Klo[out + 32] = l;
        }
    }
}

// ---------------------------------------------------------------------------
// O-projection GEMM (bf16 3-term): C = A @ Wo^T + bo, fp32 out.
// ---------------------------------------------------------------------------
__global__ __launch_bounds__(256, 1) void gemm_bf16_kernel(
    const __nv_bfloat16* __restrict__ Ahi, const __nv_bfloat16* __restrict__ Alo,
    const __nv_bfloat16* __restrict__ Whi, const __nv_bfloat16* __restrict__ Wlo,
    const float* __restrict__ bias, float* __restrict__ C,
    int M, int N, int K)
{
    extern __shared__ char sm[];
    const uint32_t smb = smem_u32(sm);
    const int tid = threadIdx.x;
    const int wid = tid >> 5, lid = tid & 31;
    const int bm = blockIdx.y * 128, bn = blockIdx.x * 128;
    const int warp_m = wid & 1, warp_n = wid >> 1;

    const __nv_bfloat16* srcs[4] = {
        Ahi + (size_t)bm * K, Alo + (size_t)bm * K,
        Whi + (size_t)bn * K, Wlo + (size_t)bn * K };

    const int arow = lid & 15;
    const int ak16 = (lid & 16);
    const int brow = (lid & 7) | ((lid & 16) >> 1);
    const int bk16 = (lid & 8) * 2;
    const uint32_t aBase = smb + (uint32_t)(warp_m * 64 + arow) * 80 + ak16;
    const uint32_t bBase = smb + 20480u + (uint32_t)(warp_n * 32 + brow) * 80 + bk16;

    float acc[4][4][4];
#pragma unroll
    for (int i = 0; i < 4; i++)
#pragma unroll
        for (int j = 0; j < 4; j++)
#pragma unroll
            for (int v = 0; v < 4; v++) acc[i][j][v] = 0.f;

    auto issue = [&](int ck) {
        const uint32_t base = smb + (uint32_t)(ck & 3) * GSTAGE;
        const int k0 = ck * 32;
#pragma unroll
        for (int a = 0; a < 4; a++) {
#pragma unroll
            for (int i = 0; i < 2; i++) {
                int idx = tid + i * 256;
                int row = idx >> 2, q = idx & 3;
                cp16(base + a * 10240 + row * 80 + q * 16,
                     srcs[a] + (size_t)row * K + k0 + q * 8);
            }
        }
    };

    issue(0); CP_COMMIT();
    issue(1); CP_COMMIT();
    issue(2); CP_COMMIT();

    const int nchunks = K / 32;
    for (int ck = 0; ck < nchunks; ck++) {
        CP_WAIT(2);
        __syncthreads();
        if (ck + 3 < nchunks) issue(ck + 3);
        CP_COMMIT();

        const uint32_t bo = (uint32_t)(ck & 3) * GSTAGE;
#pragma unroll
        for (int kk = 0; kk < 2; kk++) {
            uint32_t ah[4][4], alo[4][4], bh[2][4], blo[2][4];
            const uint32_t ka = aBase + bo + kk * 32;
            const uint32_t kb = bBase + bo + kk * 32;
#pragma unroll
            for (int mt = 0; mt < 4; mt++) {
                ldsm4(ah[mt],  ka + mt * 1280);
                ldsm4(alo[mt], ka + 10240 + mt * 1280);
            }
#pragma unroll
            for (int p = 0; p < 2; p++) {
                ldsm4(bh[p],  kb + p * 1280);
                ldsm4(blo[p], kb + 10240 + p * 1280);
            }
#pragma unroll
            for (int mt = 0; mt < 4; mt++)
#pragma unroll
                for (int nt = 0; nt < 4; nt++) {
                    const uint32_t* bhp = &bh[nt >> 1][(nt & 1) * 2];
                    const uint32_t* blp = &blo[nt >> 1][(nt & 1) * 2];
                    mma_bf16(acc[mt][nt], ah[mt], bhp);
                    mma_bf16(acc[mt][nt], ah[mt], blp);
                    mma_bf16(acc[mt][nt], alo[mt], bhp);
                }
        }
    }

    const int gr = lid >> 2, gc = lid & 3;
#pragma unroll
    for (int nt = 0; nt < 4; nt++) {
        const int col = bn + warp_n * 32 + nt * 8 + gc * 2;
        const float2 bv = *(const float2*)(bias + col);
#pragma unroll
        for (int mt = 0; mt < 4; mt++) {
            const int row = bm + warp_m * 64 + mt * 16 + gr;
            *(float2*)(C + (size_t)row * N + col) =
                make_float2(acc[mt][nt][0] + bv.x, acc[mt][nt][1] + bv.y);
            *(float2*)(C + (size_t)(row + 8) * N + col) =
                make_float2(acc[mt][nt][2] + bv.x, acc[mt][nt][3] + bv.y);
        }
    }
}

// ---------------------------------------------------------------------------
// HMMA causal flash attention, fp16 2-term. BR=128 (8 warps x 16 rows), BC=64.
// S = Q(Kh+Kl), O += P(Vh+Vl); Q,P single fp16 (err 2^-12). Online softmax
// in exp2 domain (scale folded into Q). P never leaves registers.
// smem: Q[128x144B] + 2 stages x {Khi,Klo,Vhi,Vlo}[64x144B] = 90 KB
// ---------------------------------------------------------------------------
#define AQ_B   18432            // 128*144
#define AARR_B 9216             // 64*144
#define ASTG_B (4 * AARR_B)     // 36864
#define ASMEM_TOTAL (AQ_B + 2 * ASTG_B)   // 92160

__global__ __launch_bounds__(256, 1) void attn_mma_kernel()
{
    extern __shared__ char sm[];
    const uint32_t smb = smem_u32(sm);
    const int tid = threadIdx.x;
    const int w = tid >> 5, lane = tid & 31;
    const int gr = lane >> 2, gc = lane & 3;
    const int qt = (int)gridDim.x - 1 - (int)blockIdx.x;   // long blocks first
    const int h = blockIdx.y, b = blockIdx.z;

    const size_t hb = ((size_t)b * SS) * DD + (size_t)h * HDIM;
    const size_t qrow0 = (size_t)qt * 128;

    // --- prologue: Q tile (single fp16) ---
#pragma unroll
    for (int i = 0; i < 4; i++) {
        int idx = tid + i * 256;          // 1024 chunks
        int row = idx >> 3, c = idx & 7;
        cp16(smb + row * 144 + c * 16, g_Qh + hb + (qrow0 + row) * DD + c * 8);
    }
    CP_COMMIT();

    auto stage_load = [&](int jt, int s) {
        const __half* ks[4] = { g_Khi, g_Klo, g_Vhi, g_Vlo };
        const uint32_t base = smb + AQ_B + (uint32_t)s * ASTG_B;
#pragma unroll
        for (int a = 0; a < 4; a++)
#pragma unroll
            for (int i = 0; i < 2; i++) {
                int idx = tid + i * 256;   // 512 chunks / array
                int row = idx >> 3, c = idx & 7;
                cp16(base + a * AARR_B + row * 144 + c * 16,
                     ks[a] + hb + (size_t)(jt * 64 + row) * DD + c * 8);
            }
    };
    stage_load(0, 0); CP_COMMIT();

    float m0 = -1e30f, m1 = -1e30f, l0 = 0.f, l1 = 0.f;
    float o[8][4];
#pragma unroll
    for (int d = 0; d < 8; d++)
#pragma unroll
        for (int v = 0; v < 4; v++) o[d][v] = 0.f;

    uint32_t aQ[4][4];

    const int qrow_lo = qt * 128 + w * 16 + gr;
    const int ntiles = 2 * qt + 2;

    for (int jt = 0; jt < ntiles; jt++) {
        CP_WAIT(0);
        __syncthreads();
        if (jt + 1 < ntiles) stage_load(jt + 1, (jt + 1) & 1);
        CP_COMMIT();

        if (jt == 0) {   // Q fragments (loop-invariant)
            const uint32_t qa = smb + (uint32_t)(w * 16 + (lane & 15)) * 144
                                + (lane >> 4) * 16;
#pragma unroll
            for (int kt = 0; kt < 4; kt++) ldsm4(aQ[kt], qa + kt * 32);
        }

        const uint32_t stg = smb + AQ_B + (uint32_t)(jt & 1) * ASTG_B;

        // ---- S = Q (Kh + Kl) ----
        float sc[8][4];
#pragma unroll
        for (int nt = 0; nt < 8; nt++)
#pragma unroll
            for (int v = 0; v < 4; v++) sc[nt][v] = 0.f;

        const uint32_t kaddr = stg
            + (uint32_t)((lane & 7) | ((lane & 16) >> 1)) * 144 + (lane & 8) * 2;
#pragma unroll
        for (int kt = 0; kt < 4; kt++) {
            uint32_t bKh[4][4], bKl[4][4];
#pragma unroll
            for (int np = 0; np < 4; np++) {
                ldsm4(bKh[np], kaddr + np * 2304 + kt * 32);
                ldsm4(bKl[np], kaddr + AARR_B + np * 2304 + kt * 32);
            }
#pragma unroll
            for (int np = 0; np < 4; np++) {
                mma_f16(sc[2*np],   aQ[kt], &bKh[np][0]);
                mma_f16(sc[2*np+1], aQ[kt], &bKh[np][2]);
                mma_f16(sc[2*np],   aQ[kt], &bKl[np][0]);
                mma_f16(sc[2*np+1], aQ[kt], &bKl[np][2]);
            }
        }

        // ---- causal mask (only last two tiles) ----
        if (jt >= 2 * qt) {
#pragma unroll
            for (int nt = 0; nt < 8; nt++) {
                int j = jt * 64 + nt * 8 + gc * 2;
                if (j     > qrow_lo)     sc[nt][0] = -1e30f;
                if (j + 1 > qrow_lo)     sc[nt][1] = -1e30f;
                if (j     > qrow_lo + 8) sc[nt][2] = -1e30f;
                if (j + 1 > qrow_lo + 8) sc[nt][3] = -1e30f;
            }
        }

        // ---- online softmax (exp2 domain) ----
        float mx0 = -1e30f, mx1 = -1e30f;
#pragma unroll
        for (int nt = 0; nt < 8; nt++) {
            mx0 = fmaxf(mx0, fmaxf(sc[nt][0], sc[nt][1]));
            mx1 = fmaxf(mx1, fmaxf(sc[nt][2], sc[nt][3]));
        }
        mx0 = fmaxf(mx0, __shfl_xor_sync(0xffffffffu, mx0, 1));
        mx0 = fmaxf(mx0, __shfl_xor_sync(0xffffffffu, mx0, 2));
        mx1 = fmaxf(mx1, __shfl_xor_sync(0xffffffffu, mx1, 1));
        mx1 = fmaxf(mx1, __shfl_xor_sync(0xffffffffu, mx1, 2));

        float mn0 = fmaxf(m0, mx0), mn1 = fmaxf(m1, mx1);
        float al0 = exp2f(m0 - mn0), al1 = exp2f(m1 - mn1);
        m0 = mn0; m1 = mn1;

        float rs0 = 0.f, rs1 = 0.f;
#pragma unroll
        for (int nt = 0; nt < 8; nt++) {
            sc[nt][0] = exp2f(sc[nt][0] - mn0);
            sc[nt][1] = exp2f(sc[nt][1] - mn0);
            sc[nt][2] = exp2f(sc[nt][2] - mn1);
            sc[nt][3] = exp2f(sc[nt][3] - mn1);
            rs0 += sc[nt][0] + sc[nt][1];
            rs1 += sc[nt][2] + sc[nt][3];
        }
        rs0 += __shfl_xor_sync(0xffffffffu, rs0, 1);
        rs0 += __shfl_xor_sync(0xffffffffu, rs0, 2);
        rs1 += __shfl_xor_sync(0xffffffffu, rs1, 1);
        rs1 += __shfl_xor_sync(0xffffffffu, rs1, 2);
        l0 = l0 * al0 + rs0;
        l1 = l1 * al1 + rs1;
#pragma unroll
        for (int d = 0; d < 8; d++) {
            o[d][0] *= al0; o[d][1] *= al0;
            o[d][2] *= al1; o[d][3] *= al1;
        }

        // ---- O += P (Vh + Vl); P single fp16 in registers ----
        const uint32_t vaddr = stg + 2 * AARR_B
            + (uint32_t)(lane & 15) * 144 + (lane >> 4) * 16;
#pragma unroll
        for (int kt = 0; kt < 4; kt++) {
            uint32_t aP[4];
            aP[0] = pack_f16(sc[2*kt][0],   sc[2*kt][1]);
            aP[1] = pack_f16(sc[2*kt][2],   sc[2*kt][3]);
            aP[2] = pack_f16(sc[2*kt+1][0], sc[2*kt+1][1]);
            aP[3] = pack_f16(sc[2*kt+1][2], sc[2*kt+1][3]);

            uint32_t bVh[4][4], bVl[4][4];
#pragma unroll
            for (int dp = 0; dp < 4; dp++) {
                ldsm4t(bVh[dp], vaddr + kt * 2304 + dp * 32);
                ldsm4t(bVl[dp], vaddr + AARR_B + kt * 2304 + dp * 32);
            }
#pragma unroll
            for (int dp = 0; dp < 4; dp++) {
                mma_f16(o[2*dp],   aP, &bVh[dp][0]);
                mma_f16(o[2*dp+1], aP, &bVh[dp][2]);
                mma_f16(o[2*dp],   aP, &bVl[dp][0]);
                mma_f16(o[2*dp+1], aP, &bVl[dp][2]);
            }
        }
    }

    // ---- epilogue: /l, split to bf16 hi/lo for O-projection ----
    const float inv0 = 1.0f / l0, inv1 = 1.0f / l1;
#pragma unroll
    for (int dt = 0; dt < 8; dt++) {
        size_t idx = hb + (qrow0 + w * 16 + gr) * DD + dt * 8 + gc * 2;
        uint32_t hh, ll;
        cvt_split2(o[dt][0] * inv0, o[dt][1] * inv0, hh, ll);
        *(uint32_t*)&g_Ahi[idx] = hh;
        *(uint32_t*)&g_Alo[idx] = ll;
        size_t idx8 = idx + 8 * DD;
        cvt_split2(o[dt][2] * inv1, o[dt][3] * inv1, hh, ll);
        *(uint32_t*)&g_Ahi[idx8] = hh;
        *(uint32_t*)&g_Alo[idx8] = ll;
    }
}

// ---------------------------------------------------------------------------
extern "C" void kernel_launch(void* const* d_in, const int* in_sizes, int n_in,
                              void* d_out, int out_size)
{
    (void)in_sizes; (void)n_in; (void)out_size;
    const float* x  = (const float*)d_in[0];
    const float* Wq = (const float*)d_in[1];
    const float* bq = (const float*)d_in[2];
    const float* Wk = (const float*)d_in[3];
    const float* bk = (const float*)d_in[4];
    const float* Wv = (const float*)d_in[5];
    const float* bv = (const float*)d_in[6];
    const float* Wo = (const float*)d_in[7];
    const float* bo = (const float*)d_in[8];
    float* out = (float*)d_out;

    __nv_bfloat16 *xh, *xl, *wqh, *wql, *wkh, *wkl, *wvh, *wvl, *woh, *wol;
    __nv_bfloat16 *ah, *al;
    cudaGetSymbolAddress((void**)&xh, g_xhi);
    cudaGetSymbolAddress((void**)&xl, g_xlo);
    cudaGetSymbolAddress((void**)&wqh, g_Wqh);
    cudaGetSymbolAddress((void**)&wql, g_Wql);
    cudaGetSymbolAddress((void**)&wkh, g_Wkh);
    cudaGetSymbolAddress((void**)&wkl, g_Wkl);
    cudaGetSymbolAddress((void**)&wvh, g_Wvh);
    cudaGetSymbolAddress((void**)&wvl, g_Wvl);
    cudaGetSymbolAddress((void**)&woh, g_Woh);
    cudaGetSymbolAddress((void**)&wol, g_Wol);
    cudaGetSymbolAddress((void**)&ah, g_Ahi);
    cudaGetSymbolAddress((void**)&al, g_Alo);

    cudaFuncSetAttribute(gemm_qkv_kernel,
                         cudaFuncAttributeMaxDynamicSharedMemorySize, GSMEM_TOTAL);
    cudaFuncSetAttribute(gemm_bf16_kernel,
                         cudaFuncAttributeMaxDynamicSharedMemorySize, GSMEM_TOTAL);
    cudaFuncSetAttribute(attn_mma_kernel,
                         cudaFuncAttributeMaxDynamicSharedMemorySize, ASMEM_TOTAL);

    const int NX4 = MM * DD / 4;
    const int NW4 = DD * DD / 4;

    rope_table_kernel<<<(SS * 32) / 256, 256>>>();
    convert_split_kernel<<<NX4 / 256, 256>>>(x,  xh,  xl,  NX4);
    convert_split_kernel<<<NW4 / 256, 256>>>(Wq, wqh, wql, NW4);
    convert_split_kernel<<<NW4 / 256, 256>>>(Wk, wkh, wkl, NW4);
    convert_split_kernel<<<NW4 / 256, 256>>>(Wv, wvh, wvl, NW4);
    convert_split_kernel<<<NW4 / 256, 256>>>(Wo, woh, wol, NW4);

    gemm_qkv_kernel<<<dim3(DD / 128, MM / 128, 3), 256, GSMEM_TOTAL>>>(
        xh, xl, wqh, wql, wkh, wkl, wvh, wvl, bq, bk, bv);

    attn_mma_kernel<<<dim3(SS / 128, HH, BB), 256, ASMEM_TOTAL>>>();

    gemm_bf16_kernel<<<dim3(DD / 128, MM / 128), 256, GSMEM_TOTAL>>>(
        ah, al, woh, wol, bo, out, MM, DD, DD);
}